// round 16
// baseline (speedup 1.0000x reference)
#include <cuda_runtime.h>
#include <cuda_bf16.h>
#include <cstdint>

#define N 8192
#define D 128
#define NB 128                   // 64-row blocks per dimension
#define NPAIRS 8256              // NB*(NB+1)/2 triangular block pairs
#define GRID 148
#define LDS 136                  // feature tile smem row stride (bf16)
#define FN_SCALE 4.539815982f    // sqrt(log2(e)/0.07)

// per-buffer smem layout (bytes); two buffers of BUFSZ
#define A_OFF  0u                // A tile 64x136 bf16 (17408); reused as eT
#define B_OFF  17408u            // B tile 64x136 bf16 (17408)
#define M1_OFF 34816u            // pass-1 masks: P(64x288) + Q(64x288)
#define M2_OFF 71680u            // pass-2 masks: P(64x288) + Q(64x288)
#define MQOFF  18432u            // Q offset within a mask region
#define MROW   288u              // mask smem row stride (72 words, 8 mod 32)
#define ETROW  144u              // eT row stride bytes
#define BUFSZ  108544u
#define SMEM_BYTES 217088

#define NTHREADS 256

__device__ __nv_bfloat16 g_fn[N * D];
__device__ float g_pos[N];
__device__ float g_neg[N];

__device__ __forceinline__ float ex2f(float x) {
    float y;
    asm("ex2.approx.ftz.f32 %0, %1;" : "=f"(y) : "f"(x));
    return y;
}

// mask (0/1) -> float via single IMAD: bits = m * 0x3F800000
__device__ __forceinline__ float m2f(int m) {
    return __int_as_float(m * 0x3F800000);
}

__device__ __forceinline__ void mma16816(float d[4], const uint32_t a[4],
                                         uint32_t b0, uint32_t b1) {
    asm volatile(
        "mma.sync.aligned.m16n8k16.row.col.f32.bf16.bf16.f32 "
        "{%0,%1,%2,%3}, {%4,%5,%6,%7}, {%8,%9}, {%0,%1,%2,%3};"
        : "+f"(d[0]), "+f"(d[1]), "+f"(d[2]), "+f"(d[3])
        : "r"(a[0]), "r"(a[1]), "r"(a[2]), "r"(a[3]), "r"(b0), "r"(b1));
}

__device__ __forceinline__ void cp16(uint32_t dst, const void* src) {
    asm volatile("cp.async.cg.shared.global [%0], [%1], 16;" :: "r"(dst), "l"(src));
}

// copy a 64x64 int32 block pair (P then Q) into a mask region, all 256 threads
__device__ __forceinline__ void copy_mask_block(uint32_t mb,
                                                const int* __restrict__ pm,
                                                const int* __restrict__ nm,
                                                int row0, int col0, int tid) {
#pragma unroll
    for (int k2 = 0; k2 < 8; k2++) {
        int i = tid + k2 * 256;           // 0..2047 16B chunks
        const int* mp = (i & 1024) ? nm : pm;
        uint32_t moff = (i & 1024) ? MQOFF : 0u;
        int r = (i >> 4) & 63, ch = i & 15;
        cp16(mb + moff + (uint32_t)r * MROW + (uint32_t)ch * 16,
             mp + (size_t)(row0 + r) * N + col0 + ch * 4);
    }
}

// issue ALL of one pair's data (features + both mask blocks) into a buffer
__device__ __forceinline__ void issue_pair(uint32_t buf,
                                           const int* __restrict__ pm,
                                           const int* __restrict__ nm,
                                           int m0, int j0, int tid) {
#pragma unroll
    for (int k2 = 0; k2 < 4; k2++) {
        int i = tid + k2 * 256;           // 0..1023 chunks
        int r = i >> 4, c = i & 15;
        cp16(buf + A_OFF + (uint32_t)((r * LDS + c * 8) * 2),
             g_fn + (size_t)(m0 + r) * D + c * 8);
        cp16(buf + B_OFF + (uint32_t)((r * LDS + c * 8) * 2),
             g_fn + (size_t)(j0 + r) * D + c * 8);
    }
    copy_mask_block(buf + M1_OFF, pm, nm, m0, j0, tid);
    copy_mask_block(buf + M2_OFF, pm, nm, j0, m0, tid);   // diag: unused dup
    asm volatile("cp.async.commit_group;");
}

// decode upper-triangular 64-block pair index k -> (I, J), 0 <= I <= J < 128
__device__ __forceinline__ void decode_pair(int k, int& I, int& J) {
    I = (int)((257.0f - sqrtf(66049.0f - 8.0f * (float)k)) * 0.5f);
    while ((I * (257 - I)) / 2 > k) I--;
    while (((I + 1) * (256 - I)) / 2 <= k) I++;
    J = I + (k - (I * (257 - I)) / 2);
}

// ---------------------------------------------------------------------------
// Kernel 1: L2-normalize rows (exp scale folded) + zero accumulators.
// ---------------------------------------------------------------------------
__global__ void normalize_kernel(const float* __restrict__ f) {
    int z = blockIdx.x * 256 + threadIdx.x;
    if (z < N) g_pos[z] = 0.f;
    else if (z < 2 * N) g_neg[z - N] = 0.f;

    int warp = threadIdx.x >> 5, lane = threadIdx.x & 31;
    int row0 = blockIdx.x * 16 + warp * 2;
    const float4 v0 = ((const float4*)(f + (size_t)row0 * D))[lane];
    const float4 v1 = ((const float4*)(f + (size_t)(row0 + 1) * D))[lane];
    float s0 = v0.x * v0.x + v0.y * v0.y + v0.z * v0.z + v0.w * v0.w;
    float s1 = v1.x * v1.x + v1.y * v1.y + v1.z * v1.z + v1.w * v1.w;
#pragma unroll
    for (int o = 16; o > 0; o >>= 1) {
        s0 += __shfl_xor_sync(0xffffffffu, s0, o);
        s1 += __shfl_xor_sync(0xffffffffu, s1, o);
    }
    float r0 = FN_SCALE / fmaxf(sqrtf(s0), 1e-8f);
    float r1 = FN_SCALE / fmaxf(sqrtf(s1), 1e-8f);
    union { __nv_bfloat16 h[4]; uint2 u; } p0, p1;
    p0.h[0] = __float2bfloat16_rn(v0.x * r0);
    p0.h[1] = __float2bfloat16_rn(v0.y * r0);
    p0.h[2] = __float2bfloat16_rn(v0.z * r0);
    p0.h[3] = __float2bfloat16_rn(v0.w * r0);
    p1.h[0] = __float2bfloat16_rn(v1.x * r1);
    p1.h[1] = __float2bfloat16_rn(v1.y * r1);
    p1.h[2] = __float2bfloat16_rn(v1.z * r1);
    p1.h[3] = __float2bfloat16_rn(v1.w * r1);
    ((uint2*)(g_fn + (size_t)row0 * D))[lane] = p0.u;
    ((uint2*)(g_fn + (size_t)(row0 + 1) * D))[lane] = p1.u;
}

// ---------------------------------------------------------------------------
// Kernel 2: PERSISTENT double-buffered 64x64 block-pair Gram tiles.
// Grid=148, 1 CTA/SM, 2 x 106KB buffers. Pair i+1's full data streams while
// pair i computes; exactly one cp.async wait per pair.
// MMA: warp w -> rows (w>>1)*16..+16, cols (w&1)*32..+32. acc[4][4].
// ---------------------------------------------------------------------------
__global__ __launch_bounds__(NTHREADS, 1) void simloss_sym(const int* __restrict__ pm,
                                                           const int* __restrict__ nm) {
    extern __shared__ __align__(16) char smem[];
    const uint32_t base = (uint32_t)__cvta_generic_to_shared(smem);
    const int tid = threadIdx.x;
    const int w = tid >> 5, l = tid & 31;
    const int wr = w >> 1, wc = w & 1;

    const int ar = wr * 16 + (l & 15);
    const int ac = (l >> 4) * 8;
    const int brow = (l >> 4) * 8 + (l & 7);
    const int bcol = ((l >> 3) & 1) * 8;
    const int il0 = wr * 16 + (l >> 2), il1 = il0 + 8;

    // prologue: issue pair 0's data
    int I, J;
    decode_pair(blockIdx.x, I, J);
    issue_pair(base, pm, nm, I * 64, J * 64, tid);

    for (int i = 0; ; i++) {
        const int k = blockIdx.x + i * GRID;
        const uint32_t buf = base + (uint32_t)(i & 1) * BUFSZ;
        const int m0 = I * 64, j0 = J * 64;
        const bool isDiag = (I == J);
        const bool hasNext = (k + GRID) < NPAIRS;

        // issue next pair's data into the other buffer, then wait for ours
        if (hasNext) {
            int I2, J2;
            decode_pair(k + GRID, I2, J2);
            issue_pair(base + (uint32_t)((i + 1) & 1) * BUFSZ, pm, nm,
                       I2 * 64, J2 * 64, tid);
            I = I2; J = J2;
            asm volatile("cp.async.wait_group 1;");   // pair k's group landed
        } else {
            asm volatile("cp.async.wait_group 0;");   // drain everything
        }
        __syncthreads();   // all threads' copies for pair k visible

        // ---- MMA: 16 rows x 32 cols per warp, A frags in two k-halves ----
        float acc[4][4];
#pragma unroll
        for (int z = 0; z < 4; z++) {
            acc[z][0] = 0.f; acc[z][1] = 0.f; acc[z][2] = 0.f; acc[z][3] = 0.f;
        }
#pragma unroll 1
        for (int half = 0; half < 2; half++) {
            uint32_t a[4][4];
#pragma unroll
            for (int ks = 0; ks < 4; ks++) {
                uint32_t addr = buf + A_OFF +
                    (uint32_t)((ar * LDS + (half * 4 + ks) * 16 + ac) * 2);
                asm volatile(
                    "ldmatrix.sync.aligned.m8n8.x4.shared.b16 {%0,%1,%2,%3}, [%4];"
                    : "=r"(a[ks][0]), "=r"(a[ks][1]), "=r"(a[ks][2]), "=r"(a[ks][3])
                    : "r"(addr));
            }
#pragma unroll
            for (int ks = 0; ks < 4; ks++) {
#pragma unroll
                for (int nf2 = 0; nf2 < 2; nf2++) {
                    uint32_t addr = buf + B_OFF +
                        (uint32_t)(((wc * 32 + nf2 * 16 + brow) * LDS +
                                    (half * 4 + ks) * 16 + bcol) * 2);
                    uint32_t b0, b1, b2, b3;
                    asm volatile(
                        "ldmatrix.sync.aligned.m8n8.x4.shared.b16 {%0,%1,%2,%3}, [%4];"
                        : "=r"(b0), "=r"(b1), "=r"(b2), "=r"(b3)
                        : "r"(addr));
                    mma16816(acc[nf2 * 2], a[ks], b0, b1);
                    mma16816(acc[nf2 * 2 + 1], a[ks], b2, b3);
                }
            }
        }

        __syncthreads();   // all A reads done before eT overlays A

        // ---- pass 1: I-rows, masks (I,J) from smem; write eT ----
        char* eT = smem + (buf - base);       // overlays A region of this buffer
        const int gr0 = m0 + il0, gr1 = m0 + il1;
        float pA0 = 0.f, pA1 = 0.f, nA0 = 0.f, nA1 = 0.f;

#pragma unroll
        for (int nf = 0; nf < 4; nf++) {
            const int jcl = wc * 32 + nf * 8 + (l & 3) * 2;  // col in J block
            uint32_t mp = buf + M1_OFF + (uint32_t)il0 * MROW + (uint32_t)jcl * 4;
            uint32_t mq = mp + MQOFF;
            int2 P0, Q0, P1, Q1;
            asm volatile("ld.shared.v2.b32 {%0,%1}, [%2];" : "=r"(P0.x), "=r"(P0.y) : "r"(mp));
            asm volatile("ld.shared.v2.b32 {%0,%1}, [%2];" : "=r"(Q0.x), "=r"(Q0.y) : "r"(mq));
            asm volatile("ld.shared.v2.b32 {%0,%1}, [%2];" : "=r"(P1.x), "=r"(P1.y) : "r"(mp + 8 * MROW));
            asm volatile("ld.shared.v2.b32 {%0,%1}, [%2];" : "=r"(Q1.x), "=r"(Q1.y) : "r"(mq + 8 * MROW));

            float e00 = ex2f(acc[nf][0]);
            float e01 = ex2f(acc[nf][1]);
            float e10 = ex2f(acc[nf][2]);
            float e11 = ex2f(acc[nf][3]);

            if (!isDiag) {
                *(__nv_bfloat16*)(eT + (size_t)jcl * ETROW + il0 * 2) = __float2bfloat16_rn(e00);
                *(__nv_bfloat16*)(eT + (size_t)(jcl + 1) * ETROW + il0 * 2) = __float2bfloat16_rn(e01);
                *(__nv_bfloat16*)(eT + (size_t)jcl * ETROW + il1 * 2) = __float2bfloat16_rn(e10);
                *(__nv_bfloat16*)(eT + (size_t)(jcl + 1) * ETROW + il1 * 2) = __float2bfloat16_rn(e11);
            } else {
                const int jc = j0 + jcl;
                if (gr0 == jc)     { P0.x = 0; Q0.x = 0; }
                if (gr0 == jc + 1) { P0.y = 0; Q0.y = 0; }
                if (gr1 == jc)     { P1.x = 0; Q1.x = 0; }
                if (gr1 == jc + 1) { P1.y = 0; Q1.y = 0; }
            }
            pA0 = fmaf(e00, m2f(P0.x), fmaf(e01, m2f(P0.y), pA0));
            nA0 = fmaf(e00, m2f(Q0.x), fmaf(e01, m2f(Q0.y), nA0));
            pA1 = fmaf(e10, m2f(P1.x), fmaf(e11, m2f(P1.y), pA1));
            nA1 = fmaf(e10, m2f(Q1.x), fmaf(e11, m2f(Q1.y), nA1));
        }

#pragma unroll
        for (int o = 1; o < 4; o <<= 1) {
            pA0 += __shfl_xor_sync(0xffffffffu, pA0, o);
            pA1 += __shfl_xor_sync(0xffffffffu, pA1, o);
            nA0 += __shfl_xor_sync(0xffffffffu, nA0, o);
            nA1 += __shfl_xor_sync(0xffffffffu, nA1, o);
        }
        if ((l & 3) == 0) {
            atomicAdd(&g_pos[gr0], pA0);
            atomicAdd(&g_neg[gr0], nA0);
            atomicAdd(&g_pos[gr1], pA1);
            atomicAdd(&g_neg[gr1], nA1);
        }

        __syncthreads();   // eT fully written before pass-2 reads

        // ---- pass 2 (off-diag): J-rows, masks (J,I) from M2, exp from eT ----
        if (!isDiag) {
            const int jl = w * 8 + (l >> 2);      // warp w -> J-rows w*8..+8
            const int hr = j0 + jl;
            float p2 = 0.f, n2 = 0.f;
#pragma unroll
            for (int nf = 0; nf < 8; nf++) {
                const int icl = nf * 8 + (l & 3) * 2;        // col in I block
                uint32_t mp = buf + M2_OFF + (uint32_t)jl * MROW + (uint32_t)icl * 4;
                uint32_t mq = mp + MQOFF;
                int2 P0, Q0;
                asm volatile("ld.shared.v2.b32 {%0,%1}, [%2];" : "=r"(P0.x), "=r"(P0.y) : "r"(mp));
                asm volatile("ld.shared.v2.b32 {%0,%1}, [%2];" : "=r"(Q0.x), "=r"(Q0.y) : "r"(mq));

                __nv_bfloat162 ea = *(const __nv_bfloat162*)(eT + (size_t)jl * ETROW + icl * 2);
                float f0 = __bfloat162float(ea.x), f1 = __bfloat162float(ea.y);
                p2 = fmaf(f0, m2f(P0.x), fmaf(f1, m2f(P0.y), p2));
                n2 = fmaf(f0, m2f(Q0.x), fmaf(f1, m2f(Q0.y), n2));
            }
#pragma unroll
            for (int o = 1; o < 4; o <<= 1) {
                p2 += __shfl_xor_sync(0xffffffffu, p2, o);
                n2 += __shfl_xor_sync(0xffffffffu, n2, o);
            }
            if ((l & 3) == 0) {
                atomicAdd(&g_pos[hr], p2);
                atomicAdd(&g_neg[hr], n2);
            }
        }

        __syncthreads();   // all reads of buf done before it is refilled

        if (!hasNext) break;
    }
}

// ---------------------------------------------------------------------------
// Kernel 3: final loss reduction. One block.
// ---------------------------------------------------------------------------
__global__ void loss_kernel(float* __restrict__ out) {
    __shared__ double sred[32];
    double s = 0.0;
    for (int r = threadIdx.x; r < N; r += blockDim.x) {
        float pos = g_pos[r];
        float neg = g_neg[r];
        s += (double)logf(pos / (pos + neg));
    }
#pragma unroll
    for (int o = 16; o > 0; o >>= 1) s += __shfl_xor_sync(0xffffffffu, s, o);
    int warp = threadIdx.x >> 5, lane = threadIdx.x & 31;
    if (lane == 0) sred[warp] = s;
    __syncthreads();
    if (warp == 0) {
        s = (lane < (int)(blockDim.x >> 5)) ? sred[lane] : 0.0;
#pragma unroll
        for (int o = 16; o > 0; o >>= 1) s += __shfl_xor_sync(0xffffffffu, s, o);
        if (lane == 0) out[0] = (float)(-s / (double)N);
    }
}

extern "C" void kernel_launch(void* const* d_in, const int* in_sizes, int n_in,
                              void* d_out, int out_size) {
    const float* features = (const float*)d_in[0];
    const int* pos_mask = (const int*)d_in[1];
    const int* neg_mask = (const int*)d_in[2];
    float* out = (float*)d_out;

    cudaFuncSetAttribute(simloss_sym, cudaFuncAttributeMaxDynamicSharedMemorySize,
                         SMEM_BYTES);

    normalize_kernel<<<N / 16, 256>>>(features);
    simloss_sym<<<GRID, NTHREADS, SMEM_BYTES>>>(pos_mask, neg_mask);
    loss_kernel<<<1, 1024>>>(out);
}